// round 17
// baseline (speedup 1.0000x reference)
#include <cuda_runtime.h>
#include <cuda_bf16.h>
#include <cuda_fp16.h>
#include <cuda_fp8.h>
#include <cstdint>

#define TWO_N   8192
#define N_HALF  4096
#define D       256
#define TAU_INV 10.0f
#define LOG2E10 14.426950408889634f   // 10 / ln(2)

#define SROW    272                   // padded smem row bytes (256 e4m3 + 16 pad)
#define NSLOT   256

// ---------------------------------------------------------------------------
// Scratch (allocations forbidden)
// ---------------------------------------------------------------------------
__device__ __align__(16) uint8_t g_Zfp8[TWO_N * D];  // normalized z, e4m3
__device__ float g_partial[(size_t)TWO_N * NSLOT];   // [row][slot] denominator partials
__device__ float g_rowblock[1024];
__device__ int   g_count = 0;

__device__ __forceinline__ uint32_t smem_u32(const void* p) {
    uint32_t a;
    asm("{ .reg .u64 t; cvta.to.shared.u64 t, %1; cvt.u32.u64 %0, t; }" : "=r"(a) : "l"(p));
    return a;
}
__device__ __forceinline__ void cp16(uint32_t saddr, const void* g) {
    asm volatile("cp.async.cg.shared.global [%0], [%1], 16;" :: "r"(saddr), "l"(g));
}
#define CP_COMMIT() asm volatile("cp.async.commit_group;" ::: "memory")
#define CP_WAIT0()  asm volatile("cp.async.wait_group 0;" ::: "memory")
#define CP_WAIT1()  asm volatile("cp.async.wait_group 1;" ::: "memory")

__device__ __forceinline__ void ldsm4(uint32_t* r, uint32_t addr) {
    asm volatile("ldmatrix.sync.aligned.m8n8.x4.shared.b16 {%0,%1,%2,%3}, [%4];"
                 : "=r"(r[0]), "=r"(r[1]), "=r"(r[2]), "=r"(r[3]) : "r"(addr));
}
// FP8 e4m3 MMA, m16n8k32, fp32 accumulate (A 4 regs, B 2 regs, C 4 f32)
__device__ __forceinline__ void mma_fp8(float* c, const uint32_t* a, const uint32_t* b) {
    asm volatile("mma.sync.aligned.m16n8k32.row.col.f32.e4m3.e4m3.f32 "
                 "{%0,%1,%2,%3}, {%4,%5,%6,%7}, {%8,%9}, {%0,%1,%2,%3};"
                 : "+f"(c[0]), "+f"(c[1]), "+f"(c[2]), "+f"(c[3])
                 : "r"(a[0]), "r"(a[1]), "r"(a[2]), "r"(a[3]), "r"(b[0]), "r"(b[1]));
}
__device__ __forceinline__ float exp10x(float s) {
    float e;
    asm("ex2.approx.f32 %0, %1;" : "=f"(e) : "f"(s * LOG2E10));
    return e;
}
__device__ __forceinline__ uint8_t f_to_fp8(float v) {
    return (uint8_t)__nv_cvt_float_to_fp8(v, __NV_SATFINITE, __NV_E4M3);
}
__device__ __forceinline__ float fp8_to_f(uint8_t b) {
    __half_raw hr = __nv_cvt_fp8_to_halfraw((__nv_fp8_storage_t)b, __NV_E4M3);
    return __half2float(*reinterpret_cast<__half*>(&hr));
}

// ---------------------------------------------------------------------------
// Kernel 1: L2-normalize rows into e4m3. One warp per row.
// Lane L writes cols [4L..4L+3] and [128+4L..128+4L+3].
// ---------------------------------------------------------------------------
__global__ void normalize_kernel(const float* __restrict__ x1, const float* __restrict__ x2) {
    int gw = (blockIdx.x * blockDim.x + threadIdx.x) >> 5;
    int lane = threadIdx.x & 31;
    if (gw >= TWO_N) return;
    const float4* src = (const float4*)((gw < N_HALF) ? (x1 + (size_t)gw * D)
                                                      : (x2 + (size_t)(gw - N_HALF) * D));
    float4 a = src[lane];
    float4 b = src[lane + 32];
    float ss = a.x*a.x + a.y*a.y + a.z*a.z + a.w*a.w
             + b.x*b.x + b.y*b.y + b.z*b.z + b.w*b.w;
    #pragma unroll
    for (int o = 16; o > 0; o >>= 1) ss += __shfl_xor_sync(0xffffffffu, ss, o);
    float inv = 1.0f / fmaxf(sqrtf(ss), 1e-12f);
    uint32_t pa = (uint32_t)f_to_fp8(a.x * inv)
                | ((uint32_t)f_to_fp8(a.y * inv) << 8)
                | ((uint32_t)f_to_fp8(a.z * inv) << 16)
                | ((uint32_t)f_to_fp8(a.w * inv) << 24);
    uint32_t pb = (uint32_t)f_to_fp8(b.x * inv)
                | ((uint32_t)f_to_fp8(b.y * inv) << 8)
                | ((uint32_t)f_to_fp8(b.z * inv) << 16)
                | ((uint32_t)f_to_fp8(b.w * inv) << 24);
    uint32_t* dst = (uint32_t*)(g_Zfp8 + (size_t)gw * D);
    dst[lane] = pa;
    dst[lane + 32] = pb;
}

// ---------------------------------------------------------------------------
// Kernel 2: FP8 QMMA GEMM over UPPER-TRIANGLE tiles (structure identical to
// R16 winner; dtype e4m3, k-chunk 32). 1056 CTAs, 512 threads.
// ---------------------------------------------------------------------------
#define SMEM_A   0
#define SMEM_B0  (128 * SROW)
#define SMEM_B1  (SMEM_B0 + 128 * SROW)
#define SMEM_TOT (SMEM_B1 + 128 * SROW)     // 104448 B

__device__ __forceinline__ void load_tile(uint32_t stile, int gRowBase, int tid) {
    const uint4* src = ((const uint4*)g_Zfp8) + (size_t)gRowBase * 16;  // 16 x 16B per row
    #pragma unroll
    for (int it = 0; it < 4; ++it) {
        int idx = it * 512 + tid;            // 0..2047 16B chunks
        int row = idx >> 4, c16 = idx & 15;
        cp16(stile + (uint32_t)(row * SROW + c16 * 16), src + (size_t)row * 16 + c16);
    }
}

__global__ __launch_bounds__(512, 1) void sim_kernel() {
    extern __shared__ char smem[];
    const uint32_t sbase = smem_u32(smem);
    const uint32_t sA = sbase + SMEM_A;
    const uint32_t sB0 = sbase + SMEM_B0;
    const uint32_t sB1 = sbase + SMEM_B1;

    const int tid = threadIdx.x;
    const int lane = tid & 31, wid = tid >> 5;
    const int wm = wid & 3;                  // m quarter (32 rows)
    const int wn = wid >> 2;                 // n quarter (32 cols)

    // Decode blockIdx.x -> (rt, ct0, ntiles): strips of 2 ct-tiles per rt.
    int k = blockIdx.x, rt = 0;
    while (true) {
        int ns = (65 - rt) >> 1;
        if (k < ns) break;
        k -= ns; ++rt;
    }
    const int ct0 = rt + 2 * k;
    const int ntiles = (ct0 + 1 < 64) ? 2 : 1;
    const int rowBase = rt * 128;

    load_tile(sA, rowBase, tid);
    load_tile(sB0, ct0 * 128, tid);
    CP_COMMIT();
    if (ntiles == 2) { load_tile(sB1, (ct0 + 1) * 128, tid); CP_COMMIT(); }

    // FP8 fragment lane addressing.
    // A (per mf of 16 rows): lanes {0-7,8-15} -> rows 0-15 @k+0; {16-23,24-31} -> rows 0-15 @k+16.
    const uint32_t aBase = sA + (uint32_t)((wm * 32 + (lane & 15)) * SROW + (lane >> 4) * 16);
    // B: matrix order {n0-7,k0},{n0-7,k16},{n8-15,k0},{n8-15,k16}
    const int b_n = (((lane >> 4) & 1) << 3) + (lane & 7);
    const int b_koff = ((lane >> 3) & 1) * 16;
    const uint32_t bOff = (uint32_t)((wn * 32 + b_n) * SROW + b_koff);

    #pragma unroll 1
    for (int t = 0; t < ntiles; ++t) {
        if (t == 0) { if (ntiles == 2) { CP_WAIT1(); } else { CP_WAIT0(); } }
        else       { CP_WAIT0(); }
        __syncthreads();

        const int ct = ct0 + t;
        const uint32_t sB = ((t == 0) ? sB0 : sB1) + bOff;

        float c[2][4][4];
        #pragma unroll
        for (int mf = 0; mf < 2; ++mf)
            #pragma unroll
            for (int nf = 0; nf < 4; ++nf)
                #pragma unroll
                for (int q = 0; q < 4; ++q) c[mf][nf][q] = 0.0f;

        #pragma unroll
        for (int kb = 0; kb < 8; ++kb) {     // 8 k-chunks of 32 e4m3
            uint32_t af[2][4], bf[4][2];
            #pragma unroll
            for (int mf = 0; mf < 2; ++mf)
                ldsm4(af[mf], aBase + (uint32_t)(mf * 16 * SROW + kb * 32));
            #pragma unroll
            for (int h = 0; h < 2; ++h) {    // two pairs of n-octets
                uint32_t r4[4];
                ldsm4(r4, sB + (uint32_t)(h * 16 * SROW + kb * 32));
                bf[h*2][0] = r4[0]; bf[h*2][1] = r4[1];     // octet h*2   (b0=k0-15, b1=k16-31)
                bf[h*2+1][0] = r4[2]; bf[h*2+1][1] = r4[3]; // octet h*2+1
            }
            #pragma unroll
            for (int mf = 0; mf < 2; ++mf)
                #pragma unroll
                for (int nf = 0; nf < 4; ++nf)
                    mma_fp8(c[mf][nf], af[mf], bf[nf]);
        }

        // ---- Epilogue: exp once, accumulate row sums AND column sums ----
        float rowAcc[4] = {0.f, 0.f, 0.f, 0.f};
        float colv[4][2];
        #pragma unroll
        for (int nf = 0; nf < 4; ++nf) { colv[nf][0] = 0.f; colv[nf][1] = 0.f; }

        #pragma unroll
        for (int mf = 0; mf < 2; ++mf)
            #pragma unroll
            for (int nf = 0; nf < 4; ++nf) {
                float e0 = exp10x(c[mf][nf][0]);
                float e1 = exp10x(c[mf][nf][1]);
                float e2 = exp10x(c[mf][nf][2]);
                float e3 = exp10x(c[mf][nf][3]);
                rowAcc[mf*2+0] += e0 + e1;
                rowAcc[mf*2+1] += e2 + e3;
                colv[nf][0]    += e0 + e2;
                colv[nf][1]    += e1 + e3;
            }

        #pragma unroll
        for (int i = 0; i < 4; ++i) {
            rowAcc[i] += __shfl_xor_sync(0xffffffffu, rowAcc[i], 1);
            rowAcc[i] += __shfl_xor_sync(0xffffffffu, rowAcc[i], 2);
        }
        if ((lane & 3) == 0) {
            int rbase = rowBase + wm * 32 + (lane >> 2);
            #pragma unroll
            for (int i = 0; i < 4; ++i) {
                int r = rbase + (i >> 1) * 16 + (i & 1) * 8;
                g_partial[(size_t)r * NSLOT + ct * 4 + wn] = rowAcc[i];
            }
        }

        if (ct != rt) {
            #pragma unroll
            for (int nf = 0; nf < 4; ++nf)
                #pragma unroll
                for (int s = 0; s < 2; ++s) {
                    float v = colv[nf][s];
                    v += __shfl_xor_sync(0xffffffffu, v, 4);
                    v += __shfl_xor_sync(0xffffffffu, v, 8);
                    v += __shfl_xor_sync(0xffffffffu, v, 16);
                    colv[nf][s] = v;
                }
            if (lane < 4) {
                #pragma unroll
                for (int nf = 0; nf < 4; ++nf)
                    #pragma unroll
                    for (int s = 0; s < 2; ++s) {
                        int cIdx = ct * 128 + wn * 32 + nf * 8 + 2 * lane + s;
                        g_partial[(size_t)cIdx * NSLOT + rt * 4 + wm] = colv[nf][s];
                    }
            }
        }
    }
}

// ---------------------------------------------------------------------------
// Kernel 3: per-row loss (warp per row, fp32 dots over the SAME e4m3 z)
// + fused final reduction (last block).
// ---------------------------------------------------------------------------
__global__ void row_loss_kernel(float* __restrict__ out) {
    int tid = threadIdx.x;           // 256
    int lane = tid & 31, w = tid >> 5;
    int r = blockIdx.x * 8 + w;
    int p = (r + N_HALF) & (TWO_N - 1);
    const uint2* zr = (const uint2*)(g_Zfp8 + (size_t)r * D);
    const uint2* zp = (const uint2*)(g_Zfp8 + (size_t)p * D);
    uint2 ur = zr[lane], up = zp[lane];

    float self = 0.f, pos = 0.f;
    #pragma unroll
    for (int half = 0; half < 2; ++half) {
        uint32_t wr = half ? ur.y : ur.x;
        uint32_t wp = half ? up.y : up.x;
        #pragma unroll
        for (int q = 0; q < 4; ++q) {
            float vr = fp8_to_f((uint8_t)(wr >> (q * 8)));
            float vp = fp8_to_f((uint8_t)(wp >> (q * 8)));
            self += vr * vr;
            pos  += vr * vp;
        }
    }

    // Denominator: sum the 256 partial slots (coalesced per warp).
    const float* gp = g_partial + (size_t)r * NSLOT;
    float dsum = 0.f;
    #pragma unroll
    for (int i = 0; i < 8; ++i) dsum += gp[lane + i * 32];

    #pragma unroll
    for (int o = 16; o > 0; o >>= 1) {
        self += __shfl_xor_sync(0xffffffffu, self, o);
        pos  += __shfl_xor_sync(0xffffffffu, pos, o);
        dsum += __shfl_xor_sync(0xffffffffu, dsum, o);
    }

    __shared__ float ws[8];
    if (lane == 0) {
        float denom = dsum - exp10x(self) + 1.0f;
        ws[w] = logf(denom) - pos * TAU_INV;
    }
    __syncthreads();
    __shared__ bool is_last;
    if (tid == 0) {
        float s = 0.f;
        #pragma unroll
        for (int i = 0; i < 8; ++i) s += ws[i];
        g_rowblock[blockIdx.x] = s;
        __threadfence();
        int old = atomicAdd(&g_count, 1);
        is_last = (old == (int)gridDim.x - 1);
    }
    __syncthreads();

    if (is_last) {
        float v = g_rowblock[tid] + g_rowblock[tid + 256]
                + g_rowblock[tid + 512] + g_rowblock[tid + 768];
        #pragma unroll
        for (int o = 16; o > 0; o >>= 1) v += __shfl_xor_sync(0xffffffffu, v, o);
        __shared__ float fs[8];
        if (lane == 0) fs[w] = v;
        __syncthreads();
        if (tid == 0) {
            float s = 0.f;
            #pragma unroll
            for (int i = 0; i < 8; ++i) s += fs[i];
            out[0] = s / (float)TWO_N;
            g_count = 0;
        }
    }
}

// ---------------------------------------------------------------------------
extern "C" void kernel_launch(void* const* d_in, const int* in_sizes, int n_in,
                              void* d_out, int out_size) {
    const float* x1 = (const float*)d_in[0];
    const float* x2 = (const float*)d_in[1];
    float* out = (float*)d_out;
    (void)in_sizes; (void)n_in; (void)out_size;

    cudaFuncSetAttribute(sim_kernel, cudaFuncAttributeMaxDynamicSharedMemorySize, SMEM_TOT);

    normalize_kernel<<<TWO_N / 8, 256>>>(x1, x2);
    sim_kernel<<<1056, 512, SMEM_TOT>>>();
    row_loss_kernel<<<1024, 256>>>(out);
}